// round 12
// baseline (speedup 1.0000x reference)
#include <cuda_runtime.h>
#include <cuda_fp16.h>
#include <cstdint>

// ---------------------------------------------------------------------------
// Problem constants (fixed):
//   B=8192, T=NS=64, D=64, H=256, L=64, K=128, Mrows = 524288
//   out = [enc_gt (8192*64*128) | enc_traj (8192*64*128)] fp32
// ---------------------------------------------------------------------------
#define MROWS        524288
#define ENC_GT_ELEMS 67108864

// ------------------------- device scratch (no allocs) ----------------------
__device__ __half g_h1[(size_t)MROWS * 256];   // plain fp16 activations
__device__ __half g_h2[(size_t)MROWS * 256];
__device__ float  g_P [1048576];               // P[k][t*128+j], row stride 8192
__device__ __half g_Bp0[256 * 64];             // W0^T fp16 [N][K]
__device__ __half g_Bp1[256 * 256];            // W1^T
__device__ __half g_Bp2[64 * 256];             // W2^T
__device__ __half g_Pp [8192 * 128];           // Pcat^T fp16 [N=8192][K=128]

// ------------------------- PTX helpers ------------------------------------
__device__ __forceinline__ uint32_t smem_to_u32(const void* p) {
    uint32_t a;
    asm("{ .reg .u64 t; cvta.to.shared.u64 t, %1; cvt.u32.u64 %0, t; }"
        : "=r"(a) : "l"(p));
    return a;
}
__device__ __forceinline__ void ldsm4(uint32_t addr, uint32_t* r) {
    asm volatile("ldmatrix.sync.aligned.m8n8.x4.shared.b16 {%0,%1,%2,%3}, [%4];"
        : "=r"(r[0]), "=r"(r[1]), "=r"(r[2]), "=r"(r[3]) : "r"(addr));
}
__device__ __forceinline__ void mma16816(float* c, const uint32_t* a, const uint32_t* b) {
    asm volatile(
        "mma.sync.aligned.m16n8k16.row.col.f32.f16.f16.f32 "
        "{%0,%1,%2,%3}, {%4,%5,%6,%7}, {%8,%9}, {%0,%1,%2,%3};"
        : "+f"(c[0]), "+f"(c[1]), "+f"(c[2]), "+f"(c[3])
        : "r"(a[0]), "r"(a[1]), "r"(a[2]), "r"(a[3]), "r"(b[0]), "r"(b[1]));
}
__device__ __forceinline__ uint32_t packh2(float v0, float v1) {
    __half2 h = __halves2half2(__float2half_rn(v0), __float2half_rn(v1));
    return *reinterpret_cast<uint32_t*>(&h);
}
__device__ __forceinline__ void cp16(uint32_t dst, const void* src) {
    asm volatile("cp.async.cg.shared.global [%0], [%1], 16;"
        :: "r"(dst), "l"(src) : "memory");
}
#define CP_COMMIT() asm volatile("cp.async.commit_group;" ::: "memory")
#define CP_WAIT0()  asm volatile("cp.async.wait_group 0;"  ::: "memory")

// ---------------------------------------------------------------------------
// fp16 GEMM via mma.sync:  C[M,N] = A[M,K] @ fp16(B)^T[N,K]  (+bias, relu)
//   A_F32 = true : A fp32; exact 2-pass split a = ah + al (both fp16)
//   A_F32 = false: A plain fp16 (lda elems), single pass (cp.async staged)
//   O_HALF: C written as fp16 (rounded), else fp32
//   CPX:    block.x==0 also copies its 128x64 fp32 A tile to xdst (ld 128)
//   BM=128, BK=32, 256 threads = 8 warps (4 M x 2 N).
//   Pipeline: double-buffered smem, ONE __syncthreads per chunk.
// ---------------------------------------------------------------------------
template<int BN, bool A_F32, bool O_HALF, bool RELU, bool BIAS, bool CPX>
__global__ void __launch_bounds__(256) mma_gemm(
    const void* __restrict__ Aptr, size_t lda,
    const __half* __restrict__ Bp,
    const float* __restrict__ bias,
    void* __restrict__ Cptr, size_t ldc,
    int K, float* __restrict__ xdst)
{
    constexpr int BM = 128, BK = 32;
    constexpr int APASS = A_F32 ? 2 : 1;
    constexpr int NG   = BN / 32;                 // B ldmatrix.x4 groups per k16
    constexpr int ABUF = BM * 40;                 // halves per A sub-buffer (80B rows)
    constexpr int BBUF = BN * 40;
    constexpr int STRIDE = APASS * ABUF + BBUF;   // halves per stage
    constexpr int NBV  = BN / 64;                 // 16B B copies per thread per chunk
    extern __shared__ __align__(16) __half smem[];

    const int tid = threadIdx.x, lane = tid & 31, wid = tid >> 5;
    const int wm = wid & 3, wn = wid >> 2;
    const size_t brow = (size_t)blockIdx.y * BM;
    const int bcol = blockIdx.x * BN;
    const int nc = K / BK;

    const float*  Af = (const float*)Aptr;
    const __half* Ab = (const __half*)Aptr;

    float4 afr[4];                                // A_F32 staging regs

    float acc[2][2 * NG][4];
    #pragma unroll
    for (int i = 0; i < 2; i++)
        #pragma unroll
        for (int j = 0; j < 2 * NG; j++)
            #pragma unroll
            for (int q = 0; q < 4; q++) acc[i][j][q] = 0.0f;

    const uint32_t sBase = smem_to_u32(smem);
    // lane-fixed ldmatrix byte offsets within a stage
    const uint32_t offA = (uint32_t)((wm * 32 + (lane & 15)) * 80 + (lane >> 4) * 16);
    const uint32_t rB   = (uint32_t)(wn * (BN / 2) + ((lane & 7) | (((lane >> 4) & 1) << 3)));
    const uint32_t offB = (uint32_t)(APASS * ABUF * 2) + rB * 80 + (((lane >> 3) & 1) * 16);

    // per-thread fixed smem copy slots
    const int rb4 = tid >> 2, cb4 = tid & 3;      // r = g>>2, c4 = g&3 (g = tid + i*256)

    // issue cp.async copies for chunk c into stage buf (B always; A if fp16)
    auto issue_cp = [&](int c, int buf) {
        const int k0 = c * BK;
        const uint32_t stage = sBase + (uint32_t)buf * (STRIDE * 2);
        if (!A_F32) {
            #pragma unroll
            for (int i = 0; i < 2; i++) {
                const int r = rb4 + i * 64;
                cp16(stage + (uint32_t)(r * 40 + cb4 * 8) * 2,
                     Ab + (brow + r) * lda + k0 + cb4 * 8);
            }
        }
        #pragma unroll
        for (int i = 0; i < NBV; i++) {
            const int r = rb4 + i * 64;
            cp16(stage + (uint32_t)(APASS * ABUF + r * 40 + cb4 * 8) * 2,
                 Bp + (size_t)(bcol + r) * K + k0 + cb4 * 8);
        }
        CP_COMMIT();
    };

    auto ldA_regs = [&](int c) {
        const int k0 = c * BK;
        #pragma unroll
        for (int i = 0; i < 4; i++) {
            const int g = tid + i * 256, r = g >> 3, c4 = g & 7;
            afr[i] = *reinterpret_cast<const float4*>(
                Af + (brow + r) * lda + k0 + c4 * 4);
        }
    };
    auto stA = [&](int buf) {
        __half* Ah = smem + buf * STRIDE;
        __half* Al = Ah + ABUF;
        #pragma unroll
        for (int i = 0; i < 4; i++) {
            const int g = tid + i * 256, r = g >> 3, c4 = g & 7;
            const float vv[4] = {afr[i].x, afr[i].y, afr[i].z, afr[i].w};
            float hf[4];
            #pragma unroll
            for (int j = 0; j < 4; j++)
                hf[j] = __half2float(__float2half_rn(vv[j]));
            const uint32_t H0 = packh2(vv[0], vv[1]);
            const uint32_t H1 = packh2(vv[2], vv[3]);
            const uint32_t L0 = packh2(vv[0] - hf[0], vv[1] - hf[1]);
            const uint32_t L1 = packh2(vv[2] - hf[2], vv[3] - hf[3]);
            *reinterpret_cast<uint2*>(Ah + r * 40 + c4 * 4) = make_uint2(H0, H1);
            *reinterpret_cast<uint2*>(Al + r * 40 + c4 * 4) = make_uint2(L0, L1);
        }
    };

    // prologue: stage 0
    if (A_F32) ldA_regs(0);
    issue_cp(0, 0);
    if (A_F32) stA(0);

    for (int c = 0; c < nc; c++) {
        const int buf = c & 1;
        CP_WAIT0();
        __syncthreads();                      // stage[buf] fully visible; buf^1 free
        if (c + 1 < nc) {
            if (A_F32) ldA_regs(c + 1);
            issue_cp(c + 1, buf ^ 1);
            if (A_F32) stA(buf ^ 1);          // writes buf^1, overlaps MMA on buf
        }
        const uint32_t stage = sBase + (uint32_t)buf * (STRIDE * 2);
        const uint32_t bAddr = stage + offB;
        #pragma unroll
        for (int kk = 0; kk < 2; kk++) {
            uint32_t b[NG][4];
            #pragma unroll
            for (int g = 0; g < NG; g++)
                ldsm4(bAddr + g * (16 * 80) + kk * 32, b[g]);
            #pragma unroll
            for (int p = 0; p < APASS; p++) {
                uint32_t a[2][4];
                const uint32_t aAddr = stage + (uint32_t)(p * ABUF * 2) + offA;
                #pragma unroll
                for (int mt = 0; mt < 2; mt++)
                    ldsm4(aAddr + mt * (16 * 80) + kk * 32, a[mt]);
                #pragma unroll
                for (int mt = 0; mt < 2; mt++)
                    #pragma unroll
                    for (int g = 0; g < NG; g++) {
                        mma16816(acc[mt][2 * g],     a[mt], &b[g][0]);
                        mma16816(acc[mt][2 * g + 1], a[mt], &b[g][2]);
                    }
            }
        }
    }

    // ---- optional x copy (GEMM1, block.x == 0): enc_gt[:, 0:64] = x ----
    if (CPX && blockIdx.x == 0) {
        #pragma unroll
        for (int i = 0; i < 8; i++) {
            const int g = tid + i * 256, r = g >> 4, cc = (g & 15) * 4;
            *reinterpret_cast<float4*>(xdst + (brow + r) * 128 + cc) =
                *reinterpret_cast<const float4*>(Af + (brow + r) * lda + cc);
        }
    }

    // ---- epilogue ----
    #pragma unroll
    for (int mt = 0; mt < 2; mt++) {
        #pragma unroll
        for (int nt = 0; nt < 2 * NG; nt++) {
            const size_t row = brow + wm * 32 + mt * 16 + (lane >> 2);
            const int    col = bcol + wn * (BN / 2) + nt * 8 + (lane & 3) * 2;
            float v0 = acc[mt][nt][0], v1 = acc[mt][nt][1];
            float v2 = acc[mt][nt][2], v3 = acc[mt][nt][3];
            if (BIAS) {
                const float bb0 = bias[col], bb1 = bias[col + 1];
                v0 += bb0; v1 += bb1; v2 += bb0; v3 += bb1;
            }
            if (RELU) {
                v0 = fmaxf(v0, 0.0f); v1 = fmaxf(v1, 0.0f);
                v2 = fmaxf(v2, 0.0f); v3 = fmaxf(v3, 0.0f);
            }
            if (O_HALF) {
                __half* Cb = (__half*)Cptr;
                *reinterpret_cast<uint32_t*>(Cb + row * ldc + col)       = packh2(v0, v1);
                *reinterpret_cast<uint32_t*>(Cb + (row + 8) * ldc + col) = packh2(v2, v3);
            } else {
                float* Cf = (float*)Cptr;
                *reinterpret_cast<float2*>(Cf + row * ldc + col)       = make_float2(v0, v1);
                *reinterpret_cast<float2*>(Cf + (row + 8) * ldc + col) = make_float2(v2, v3);
            }
        }
    }
}

// ---------------------------------------------------------------------------
// fp32 Koopman matrix powers (log-doubling) — exact
// ---------------------------------------------------------------------------
__global__ void init_powers(const float* __restrict__ ko)
{
    int i = blockIdx.x * blockDim.x + threadIdx.x;
    int r = i >> 7, c = i & 127;
    g_P[r * 8192 + c]       = (r == c) ? 1.0f : 0.0f;
    g_P[r * 8192 + 128 + c] = ko[i];
}

__global__ void __launch_bounds__(256) power_stage(int m)
{
    const int t = blockIdx.x + 1;
    if (m + t > 63) return;
    const float* Pt = g_P + t * 128;
    const float* Pm = g_P + m * 128;
    float*       Pd = g_P + (m + t) * 128;

    __shared__ float sPm [32][128];
    __shared__ float sPtT[32][128];

    const int tid   = threadIdx.x;
    const int r     = tid >> 1;
    const int cbase = (tid & 1) * 64;

    float acc[64];
    #pragma unroll
    for (int j = 0; j < 64; j++) acc[j] = 0.0f;

    for (int kk = 0; kk < 128; kk += 32) {
        #pragma unroll
        for (int i = tid; i < 32 * 128 / 4; i += 256) {
            int rr = i >> 5, cc = (i & 31) << 2;
            *reinterpret_cast<float4*>(&sPm[rr][cc]) =
                *reinterpret_cast<const float4*>(&Pm[(kk + rr) * 8192 + cc]);
        }
        #pragma unroll
        for (int i = tid; i < 128 * 32 / 4; i += 256) {
            int rr = i >> 3, cc = (i & 7) << 2;
            float4 v = *reinterpret_cast<const float4*>(&Pt[rr * 8192 + kk + cc]);
            sPtT[cc + 0][rr] = v.x; sPtT[cc + 1][rr] = v.y;
            sPtT[cc + 2][rr] = v.z; sPtT[cc + 3][rr] = v.w;
        }
        __syncthreads();
        #pragma unroll
        for (int k = 0; k < 32; k++) {
            const float a = sPtT[k][r];
            #pragma unroll
            for (int j = 0; j < 64; j += 4) {
                float4 bv = *reinterpret_cast<const float4*>(&sPm[k][cbase + j]);
                acc[j+0] = fmaf(a, bv.x, acc[j+0]);
                acc[j+1] = fmaf(a, bv.y, acc[j+1]);
                acc[j+2] = fmaf(a, bv.z, acc[j+2]);
                acc[j+3] = fmaf(a, bv.w, acc[j+3]);
            }
        }
        __syncthreads();
    }
    #pragma unroll
    for (int j = 0; j < 64; j += 4)
        *reinterpret_cast<float4*>(&Pd[r * 8192 + cbase + j]) =
            make_float4(acc[j], acc[j+1], acc[j+2], acc[j+3]);
}

// ---------------------------------------------------------------------------
// Prep: W[K][N] fp32 -> Bp[N][K] fp16 (transpose + round)
// ---------------------------------------------------------------------------
__global__ void prep_W(const float* __restrict__ W,
                       __half* __restrict__ Bp, int K, int N)
{
    int i = blockIdx.x * 256 + threadIdx.x;
    if (i >= N * K) return;
    int n = i / K, k = i - n * K;
    Bp[i] = __float2half_rn(W[(size_t)k * N + n]);
}

// Prep: g_P[k][n] (stride 8192) -> g_Pp[n][k] fp16
__global__ void prep_P()
{
    int i = blockIdx.x * 256 + threadIdx.x;   // 8192*128
    int n = i >> 7, k = i & 127;
    g_Pp[i] = __float2half_rn(g_P[k * 8192 + n]);
}

// ---------------------------------------------------------------------------
// kernel_launch — graph-capturable (kernel launches only)
// Input order: x, W0, b0, W1, b1, W2, ko_W, n_shifts
// ---------------------------------------------------------------------------
extern "C" void kernel_launch(void* const* d_in, const int* in_sizes, int n_in,
                              void* d_out, int out_size)
{
    const float* x   = (const float*)d_in[0];
    const float* W0  = (const float*)d_in[1];
    const float* b0  = (const float*)d_in[2];
    const float* W1  = (const float*)d_in[3];
    const float* b1  = (const float*)d_in[4];
    const float* W2  = (const float*)d_in[5];
    const float* koW = (const float*)d_in[6];
    (void)in_sizes; (void)n_in; (void)out_size;

    float* out      = (float*)d_out;
    float* enc_gt   = out;
    float* enc_traj = out + ENC_GT_ELEMS;

    __half *h1, *h2, *Bp0, *Bp1, *Bp2, *Pp;
    cudaGetSymbolAddress((void**)&h1,  g_h1);
    cudaGetSymbolAddress((void**)&h2,  g_h2);
    cudaGetSymbolAddress((void**)&Bp0, g_Bp0);
    cudaGetSymbolAddress((void**)&Bp1, g_Bp1);
    cudaGetSymbolAddress((void**)&Bp2, g_Bp2);
    cudaGetSymbolAddress((void**)&Pp,  g_Pp);

    // dynamic smem per variant: STRIDE halves * 2 stages * 2 bytes
    const int SM_SPLIT128 = (2 * 128 + 128) * 40 * 2 * 2;  // 61440 (A_F32, BN=128)
    const int SM_H128     = (128 + 128) * 40 * 2 * 2;      // 40960 (fp16 A, BN=128)
    const int SM_H64      = (128 + 64)  * 40 * 2 * 2;      // 30720 (fp16 A, BN=64)
    cudaFuncSetAttribute(mma_gemm<128, true,  true,  true,  true,  true >, cudaFuncAttributeMaxDynamicSharedMemorySize, SM_SPLIT128);
    cudaFuncSetAttribute(mma_gemm<128, false, true,  true,  true,  false>, cudaFuncAttributeMaxDynamicSharedMemorySize, SM_H128);
    cudaFuncSetAttribute(mma_gemm<64,  false, false, false, false, false>, cudaFuncAttributeMaxDynamicSharedMemorySize, SM_H64);
    cudaFuncSetAttribute(mma_gemm<128, true,  false, false, false, false>, cudaFuncAttributeMaxDynamicSharedMemorySize, SM_SPLIT128);

    // weight prep (round + transpose to [N][K] fp16)
    prep_W<<<64,  256>>>(W0, Bp0, 64, 256);
    prep_W<<<256, 256>>>(W1, Bp1, 256, 256);
    prep_W<<<64,  256>>>(W2, Bp2, 256, 64);

    // h1 = relu(x @ W0 + b0)           M=524288 K=64  N=256  (+ x copy to enc_gt)
    mma_gemm<128, true, true, true, true, true><<<dim3(2, MROWS / 128), 256, SM_SPLIT128>>>(
        x, 64, Bp0, b0, h1, 256, 64, enc_gt);

    // h2 = relu(h1 @ W1 + b1)          M=524288 K=256 N=256  (fp16 in/out, 1-pass)
    mma_gemm<128, false, true, true, true, false><<<dim3(2, MROWS / 128), 256, SM_H128>>>(
        h1, 256, Bp1, b1, h2, 256, 256, nullptr);

    // enc_gt cols [64,128) = h2 @ W2   M=524288 K=256 N=64   (fp16 in, fp32 out, 1-pass)
    mma_gemm<64, false, false, false, false, false><<<dim3(1, MROWS / 128), 256, SM_H64>>>(
        h2, 256, Bp2, nullptr, enc_gt + 64, 128, 256, nullptr);

    // fp32 Koopman powers, then round for the trajectory GEMM
    init_powers<<<64, 256>>>(koW);
    for (int m = 1; m <= 32; m <<= 1)
        power_stage<<<m, 256>>>(m);
    prep_P<<<4096, 256>>>();

    // enc_traj = z0 @ [P_0 | ... | P_63]   M=8192 K=128 N=8192 (2-pass exact A)
    mma_gemm<128, true, false, false, false, false><<<dim3(64, 64), 256, SM_SPLIT128>>>(
        enc_gt, 8192, Pp, nullptr, enc_traj, 8192, 128, nullptr);
}

// round 13
// speedup vs baseline: 1.0002x; 1.0002x over previous
#include <cuda_runtime.h>
#include <cuda_fp16.h>
#include <cstdint>

// ---------------------------------------------------------------------------
// Problem constants (fixed):
//   B=8192, T=NS=64, D=64, H=256, L=64, K=128, Mrows = 524288
//   out = [enc_gt (8192*64*128) | enc_traj (8192*64*128)] fp32
// ---------------------------------------------------------------------------
#define MROWS        524288
#define ENC_GT_ELEMS 67108864

// ------------------------- device scratch (no allocs) ----------------------
__device__ __half g_h1[(size_t)MROWS * 256];   // plain fp16 activations
__device__ __half g_h2[(size_t)MROWS * 256];
__device__ float  g_P [1048576];               // P[k][t*128+j], row stride 8192
__device__ __half g_Bp0[256 * 64];             // W0^T fp16 [N][K]
__device__ __half g_Bp1[256 * 256];            // W1^T
__device__ __half g_Bp2[64 * 256];             // W2^T
__device__ __half g_Pp [8192 * 128];           // Pcat^T fp16 [N=8192][K=128]

// ------------------------- PTX helpers ------------------------------------
__device__ __forceinline__ uint32_t smem_to_u32(const void* p) {
    uint32_t a;
    asm("{ .reg .u64 t; cvta.to.shared.u64 t, %1; cvt.u32.u64 %0, t; }"
        : "=r"(a) : "l"(p));
    return a;
}
__device__ __forceinline__ void ldsm4(uint32_t addr, uint32_t* r) {
    asm volatile("ldmatrix.sync.aligned.m8n8.x4.shared.b16 {%0,%1,%2,%3}, [%4];"
        : "=r"(r[0]), "=r"(r[1]), "=r"(r[2]), "=r"(r[3]) : "r"(addr));
}
__device__ __forceinline__ void mma16816(float* c, const uint32_t* a, const uint32_t* b) {
    asm volatile(
        "mma.sync.aligned.m16n8k16.row.col.f32.f16.f16.f32 "
        "{%0,%1,%2,%3}, {%4,%5,%6,%7}, {%8,%9}, {%0,%1,%2,%3};"
        : "+f"(c[0]), "+f"(c[1]), "+f"(c[2]), "+f"(c[3])
        : "r"(a[0]), "r"(a[1]), "r"(a[2]), "r"(a[3]), "r"(b[0]), "r"(b[1]));
}
__device__ __forceinline__ uint32_t packh2(float v0, float v1) {
    __half2 h = __halves2half2(__float2half_rn(v0), __float2half_rn(v1));
    return *reinterpret_cast<uint32_t*>(&h);
}
__device__ __forceinline__ void cp16(uint32_t dst, const void* src) {
    asm volatile("cp.async.cg.shared.global [%0], [%1], 16;"
        :: "r"(dst), "l"(src) : "memory");
}
#define CP_COMMIT() asm volatile("cp.async.commit_group;" ::: "memory")
#define CP_WAIT0()  asm volatile("cp.async.wait_group 0;"  ::: "memory")

// ---------------------------------------------------------------------------
// fp16 GEMM via mma.sync:  C[M,N] = A[M,K] @ fp16(B)^T[N,K]  (+bias, relu)
//   A_F32 = true : A fp32; exact 2-pass split a = ah + al (both fp16)
//   A_F32 = false: A plain fp16 (lda elems), single pass (cp.async staged)
//   O_HALF: C written as fp16 (rounded), else fp32
//   CPX:    block.x==0 also copies its 128x64 fp32 A tile to xdst (ld 128)
//   BM=128, BK=32, 256 threads = 8 warps (4 M x 2 N).
//   Pipeline: double-buffered smem, ONE __syncthreads per chunk.
// ---------------------------------------------------------------------------
template<int BN, bool A_F32, bool O_HALF, bool RELU, bool BIAS, bool CPX>
__global__ void __launch_bounds__(256) mma_gemm(
    const void* __restrict__ Aptr, size_t lda,
    const __half* __restrict__ Bp,
    const float* __restrict__ bias,
    void* __restrict__ Cptr, size_t ldc,
    int K, float* __restrict__ xdst)
{
    constexpr int BM = 128, BK = 32;
    constexpr int APASS = A_F32 ? 2 : 1;
    constexpr int NG   = BN / 32;                 // B ldmatrix.x4 groups per k16
    constexpr int ABUF = BM * 40;                 // halves per A sub-buffer (80B rows)
    constexpr int BBUF = BN * 40;
    constexpr int STRIDE = APASS * ABUF + BBUF;   // halves per stage
    constexpr int NBV  = BN / 64;                 // 16B B copies per thread per chunk
    extern __shared__ __align__(16) __half smem[];

    const int tid = threadIdx.x, lane = tid & 31, wid = tid >> 5;
    const int wm = wid & 3, wn = wid >> 2;
    const size_t brow = (size_t)blockIdx.y * BM;
    const int bcol = blockIdx.x * BN;
    const int nc = K / BK;

    const float*  Af = (const float*)Aptr;
    const __half* Ab = (const __half*)Aptr;

    float4 afr[4];                                // A_F32 staging regs

    float acc[2][2 * NG][4];
    #pragma unroll
    for (int i = 0; i < 2; i++)
        #pragma unroll
        for (int j = 0; j < 2 * NG; j++)
            #pragma unroll
            for (int q = 0; q < 4; q++) acc[i][j][q] = 0.0f;

    const uint32_t sBase = smem_to_u32(smem);
    // lane-fixed ldmatrix byte offsets within a stage
    const uint32_t offA = (uint32_t)((wm * 32 + (lane & 15)) * 80 + (lane >> 4) * 16);
    const uint32_t rB   = (uint32_t)(wn * (BN / 2) + ((lane & 7) | (((lane >> 4) & 1) << 3)));
    const uint32_t offB = (uint32_t)(APASS * ABUF * 2) + rB * 80 + (((lane >> 3) & 1) * 16);

    // per-thread fixed smem copy slots
    const int rb4 = tid >> 2, cb4 = tid & 3;      // r = g>>2, c4 = g&3 (g = tid + i*256)

    // issue cp.async copies for chunk c into stage buf (B always; A if fp16)
    auto issue_cp = [&](int c, int buf) {
        const int k0 = c * BK;
        const uint32_t stage = sBase + (uint32_t)buf * (STRIDE * 2);
        if (!A_F32) {
            #pragma unroll
            for (int i = 0; i < 2; i++) {
                const int r = rb4 + i * 64;
                cp16(stage + (uint32_t)(r * 40 + cb4 * 8) * 2,
                     Ab + (brow + r) * lda + k0 + cb4 * 8);
            }
        }
        #pragma unroll
        for (int i = 0; i < NBV; i++) {
            const int r = rb4 + i * 64;
            cp16(stage + (uint32_t)(APASS * ABUF + r * 40 + cb4 * 8) * 2,
                 Bp + (size_t)(bcol + r) * K + k0 + cb4 * 8);
        }
        CP_COMMIT();
    };

    auto ldA_regs = [&](int c) {
        const int k0 = c * BK;
        #pragma unroll
        for (int i = 0; i < 4; i++) {
            const int g = tid + i * 256, r = g >> 3, c4 = g & 7;
            afr[i] = *reinterpret_cast<const float4*>(
                Af + (brow + r) * lda + k0 + c4 * 4);
        }
    };
    auto stA = [&](int buf) {
        __half* Ah = smem + buf * STRIDE;
        __half* Al = Ah + ABUF;
        #pragma unroll
        for (int i = 0; i < 4; i++) {
            const int g = tid + i * 256, r = g >> 3, c4 = g & 7;
            const float vv[4] = {afr[i].x, afr[i].y, afr[i].z, afr[i].w};
            float hf[4];
            #pragma unroll
            for (int j = 0; j < 4; j++)
                hf[j] = __half2float(__float2half_rn(vv[j]));
            const uint32_t H0 = packh2(vv[0], vv[1]);
            const uint32_t H1 = packh2(vv[2], vv[3]);
            const uint32_t L0 = packh2(vv[0] - hf[0], vv[1] - hf[1]);
            const uint32_t L1 = packh2(vv[2] - hf[2], vv[3] - hf[3]);
            *reinterpret_cast<uint2*>(Ah + r * 40 + c4 * 4) = make_uint2(H0, H1);
            *reinterpret_cast<uint2*>(Al + r * 40 + c4 * 4) = make_uint2(L0, L1);
        }
    };

    // prologue: stage 0
    if (A_F32) ldA_regs(0);
    issue_cp(0, 0);
    if (A_F32) stA(0);

    for (int c = 0; c < nc; c++) {
        const int buf = c & 1;
        CP_WAIT0();
        __syncthreads();                      // stage[buf] fully visible; buf^1 free
        if (c + 1 < nc) {
            if (A_F32) ldA_regs(c + 1);
            issue_cp(c + 1, buf ^ 1);
            if (A_F32) stA(buf ^ 1);          // writes buf^1, overlaps MMA on buf
        }
        const uint32_t stage = sBase + (uint32_t)buf * (STRIDE * 2);
        const uint32_t bAddr = stage + offB;
        #pragma unroll
        for (int kk = 0; kk < 2; kk++) {
            uint32_t b[NG][4];
            #pragma unroll
            for (int g = 0; g < NG; g++)
                ldsm4(bAddr + g * (16 * 80) + kk * 32, b[g]);
            #pragma unroll
            for (int p = 0; p < APASS; p++) {
                uint32_t a[2][4];
                const uint32_t aAddr = stage + (uint32_t)(p * ABUF * 2) + offA;
                #pragma unroll
                for (int mt = 0; mt < 2; mt++)
                    ldsm4(aAddr + mt * (16 * 80) + kk * 32, a[mt]);
                #pragma unroll
                for (int mt = 0; mt < 2; mt++)
                    #pragma unroll
                    for (int g = 0; g < NG; g++) {
                        mma16816(acc[mt][2 * g],     a[mt], &b[g][0]);
                        mma16816(acc[mt][2 * g + 1], a[mt], &b[g][2]);
                    }
            }
        }
    }

    // ---- optional x copy (GEMM1, block.x == 0): enc_gt[:, 0:64] = x ----
    if (CPX && blockIdx.x == 0) {
        #pragma unroll
        for (int i = 0; i < 8; i++) {
            const int g = tid + i * 256, r = g >> 4, cc = (g & 15) * 4;
            *reinterpret_cast<float4*>(xdst + (brow + r) * 128 + cc) =
                *reinterpret_cast<const float4*>(Af + (brow + r) * lda + cc);
        }
    }

    // ---- epilogue ----
    #pragma unroll
    for (int mt = 0; mt < 2; mt++) {
        #pragma unroll
        for (int nt = 0; nt < 2 * NG; nt++) {
            const size_t row = brow + wm * 32 + mt * 16 + (lane >> 2);
            const int    col = bcol + wn * (BN / 2) + nt * 8 + (lane & 3) * 2;
            float v0 = acc[mt][nt][0], v1 = acc[mt][nt][1];
            float v2 = acc[mt][nt][2], v3 = acc[mt][nt][3];
            if (BIAS) {
                const float bb0 = bias[col], bb1 = bias[col + 1];
                v0 += bb0; v1 += bb1; v2 += bb0; v3 += bb1;
            }
            if (RELU) {
                v0 = fmaxf(v0, 0.0f); v1 = fmaxf(v1, 0.0f);
                v2 = fmaxf(v2, 0.0f); v3 = fmaxf(v3, 0.0f);
            }
            if (O_HALF) {
                __half* Cb = (__half*)Cptr;
                *reinterpret_cast<uint32_t*>(Cb + row * ldc + col)       = packh2(v0, v1);
                *reinterpret_cast<uint32_t*>(Cb + (row + 8) * ldc + col) = packh2(v2, v3);
            } else {
                float* Cf = (float*)Cptr;
                *reinterpret_cast<float2*>(Cf + row * ldc + col)       = make_float2(v0, v1);
                *reinterpret_cast<float2*>(Cf + (row + 8) * ldc + col) = make_float2(v2, v3);
            }
        }
    }
}

// ---------------------------------------------------------------------------
// fp32 Koopman matrix powers (log-doubling) — exact
// ---------------------------------------------------------------------------
__global__ void init_powers(const float* __restrict__ ko)
{
    int i = blockIdx.x * blockDim.x + threadIdx.x;
    int r = i >> 7, c = i & 127;
    g_P[r * 8192 + c]       = (r == c) ? 1.0f : 0.0f;
    g_P[r * 8192 + 128 + c] = ko[i];
}

__global__ void __launch_bounds__(256) power_stage(int m)
{
    const int t = blockIdx.x + 1;
    if (m + t > 63) return;
    const float* Pt = g_P + t * 128;
    const float* Pm = g_P + m * 128;
    float*       Pd = g_P + (m + t) * 128;

    __shared__ float sPm [32][128];
    __shared__ float sPtT[32][128];

    const int tid   = threadIdx.x;
    const int r     = tid >> 1;
    const int cbase = (tid & 1) * 64;

    float acc[64];
    #pragma unroll
    for (int j = 0; j < 64; j++) acc[j] = 0.0f;

    for (int kk = 0; kk < 128; kk += 32) {
        #pragma unroll
        for (int i = tid; i < 32 * 128 / 4; i += 256) {
            int rr = i >> 5, cc = (i & 31) << 2;
            *reinterpret_cast<float4*>(&sPm[rr][cc]) =
                *reinterpret_cast<const float4*>(&Pm[(kk + rr) * 8192 + cc]);
        }
        #pragma unroll
        for (int i = tid; i < 128 * 32 / 4; i += 256) {
            int rr = i >> 3, cc = (i & 7) << 2;
            float4 v = *reinterpret_cast<const float4*>(&Pt[rr * 8192 + kk + cc]);
            sPtT[cc + 0][rr] = v.x; sPtT[cc + 1][rr] = v.y;
            sPtT[cc + 2][rr] = v.z; sPtT[cc + 3][rr] = v.w;
        }
        __syncthreads();
        #pragma unroll
        for (int k = 0; k < 32; k++) {
            const float a = sPtT[k][r];
            #pragma unroll
            for (int j = 0; j < 64; j += 4) {
                float4 bv = *reinterpret_cast<const float4*>(&sPm[k][cbase + j]);
                acc[j+0] = fmaf(a, bv.x, acc[j+0]);
                acc[j+1] = fmaf(a, bv.y, acc[j+1]);
                acc[j+2] = fmaf(a, bv.z, acc[j+2]);
                acc[j+3] = fmaf(a, bv.w, acc[j+3]);
            }
        }
        __syncthreads();
    }
    #pragma unroll
    for (int j = 0; j < 64; j += 4)
        *reinterpret_cast<float4*>(&Pd[r * 8192 + cbase + j]) =
            make_float4(acc[j], acc[j+1], acc[j+2], acc[j+3]);
}

// ---------------------------------------------------------------------------
// Prep: W[K][N] fp32 -> Bp[N][K] fp16 (transpose + round)
// ---------------------------------------------------------------------------
__global__ void prep_W(const float* __restrict__ W,
                       __half* __restrict__ Bp, int K, int N)
{
    int i = blockIdx.x * 256 + threadIdx.x;
    if (i >= N * K) return;
    int n = i / K, k = i - n * K;
    Bp[i] = __float2half_rn(W[(size_t)k * N + n]);
}

// Prep: g_P[k][n] (stride 8192) -> g_Pp[n][k] fp16
__global__ void prep_P()
{
    int i = blockIdx.x * 256 + threadIdx.x;   // 8192*128
    int n = i >> 7, k = i & 127;
    g_Pp[i] = __float2half_rn(g_P[k * 8192 + n]);
}

// ---------------------------------------------------------------------------
// kernel_launch — graph-capturable (kernel launches only)
// Input order: x, W0, b0, W1, b1, W2, ko_W, n_shifts
// ---------------------------------------------------------------------------
extern "C" void kernel_launch(void* const* d_in, const int* in_sizes, int n_in,
                              void* d_out, int out_size)
{
    const float* x   = (const float*)d_in[0];
    const float* W0  = (const float*)d_in[1];
    const float* b0  = (const float*)d_in[2];
    const float* W1  = (const float*)d_in[3];
    const float* b1  = (const float*)d_in[4];
    const float* W2  = (const float*)d_in[5];
    const float* koW = (const float*)d_in[6];
    (void)in_sizes; (void)n_in; (void)out_size;

    float* out      = (float*)d_out;
    float* enc_gt   = out;
    float* enc_traj = out + ENC_GT_ELEMS;

    __half *h1, *h2, *Bp0, *Bp1, *Bp2, *Pp;
    cudaGetSymbolAddress((void**)&h1,  g_h1);
    cudaGetSymbolAddress((void**)&h2,  g_h2);
    cudaGetSymbolAddress((void**)&Bp0, g_Bp0);
    cudaGetSymbolAddress((void**)&Bp1, g_Bp1);
    cudaGetSymbolAddress((void**)&Bp2, g_Bp2);
    cudaGetSymbolAddress((void**)&Pp,  g_Pp);

    // dynamic smem per variant: STRIDE halves * 2 stages * 2 bytes
    const int SM_SPLIT128 = (2 * 128 + 128) * 40 * 2 * 2;  // 61440 (A_F32, BN=128)
    const int SM_H128     = (128 + 128) * 40 * 2 * 2;      // 40960 (fp16 A, BN=128)
    const int SM_H64      = (128 + 64)  * 40 * 2 * 2;      // 30720 (fp16 A, BN=64)
    cudaFuncSetAttribute(mma_gemm<128, true,  true,  true,  true,  true >, cudaFuncAttributeMaxDynamicSharedMemorySize, SM_SPLIT128);
    cudaFuncSetAttribute(mma_gemm<128, false, true,  true,  true,  false>, cudaFuncAttributeMaxDynamicSharedMemorySize, SM_H128);
    cudaFuncSetAttribute(mma_gemm<64,  false, false, false, false, false>, cudaFuncAttributeMaxDynamicSharedMemorySize, SM_H64);
    cudaFuncSetAttribute(mma_gemm<128, true,  false, false, false, false>, cudaFuncAttributeMaxDynamicSharedMemorySize, SM_SPLIT128);

    // weight prep (round + transpose to [N][K] fp16)
    prep_W<<<64,  256>>>(W0, Bp0, 64, 256);
    prep_W<<<256, 256>>>(W1, Bp1, 256, 256);
    prep_W<<<64,  256>>>(W2, Bp2, 256, 64);

    // h1 = relu(x @ W0 + b0)           M=524288 K=64  N=256  (+ x copy to enc_gt)
    mma_gemm<128, true, true, true, true, true><<<dim3(2, MROWS / 128), 256, SM_SPLIT128>>>(
        x, 64, Bp0, b0, h1, 256, 64, enc_gt);

    // h2 = relu(h1 @ W1 + b1)          M=524288 K=256 N=256  (fp16 in/out, 1-pass)
    mma_gemm<128, false, true, true, true, false><<<dim3(2, MROWS / 128), 256, SM_H128>>>(
        h1, 256, Bp1, b1, h2, 256, 256, nullptr);

    // enc_gt cols [64,128) = h2 @ W2   M=524288 K=256 N=64   (fp16 in, fp32 out, 1-pass)
    mma_gemm<64, false, false, false, false, false><<<dim3(1, MROWS / 128), 256, SM_H64>>>(
        h2, 256, Bp2, nullptr, enc_gt + 64, 128, 256, nullptr);

    // fp32 Koopman powers, then round for the trajectory GEMM
    init_powers<<<64, 256>>>(koW);
    for (int m = 1; m <= 32; m <<= 1)
        power_stage<<<m, 256>>>(m);
    prep_P<<<4096, 256>>>();

    // enc_traj = z0 @ [P_0 | ... | P_63]   M=8192 K=128 N=8192 (2-pass exact A)
    mma_gemm<128, true, false, false, false, false><<<dim3(64, 64), 256, SM_SPLIT128>>>(
        enc_gt, 8192, Pp, nullptr, enc_traj, 8192, 128, nullptr);
}

// round 15
// speedup vs baseline: 1.0047x; 1.0044x over previous
#include <cuda_runtime.h>
#include <cuda_fp16.h>
#include <cstdint>

// ---------------------------------------------------------------------------
// Problem constants (fixed):
//   B=8192, T=NS=64, D=64, H=256, L=64, K=128, Mrows = 524288
//   out = [enc_gt (8192*64*128) | enc_traj (8192*64*128)] fp32
// ---------------------------------------------------------------------------
#define MROWS        524288
#define ENC_GT_ELEMS 67108864

// ------------------------- device scratch (no allocs) ----------------------
__device__ __half g_h1[(size_t)MROWS * 256];   // plain fp16 activations
__device__ __half g_h2[(size_t)MROWS * 256];
__device__ float  g_P [1048576];               // P[k][t*128+j], row stride 8192
__device__ __half g_Bp0[256 * 64];             // W0^T fp16 [N][K]
__device__ __half g_Bp1[256 * 256];            // W1^T
__device__ __half g_Bp2[64 * 256];             // W2^T
__device__ __half g_Pp [8192 * 128];           // Pcat^T fp16 [N=8192][K=128]

// ------------------------- PTX helpers ------------------------------------
__device__ __forceinline__ uint32_t smem_to_u32(const void* p) {
    uint32_t a;
    asm("{ .reg .u64 t; cvta.to.shared.u64 t, %1; cvt.u32.u64 %0, t; }"
        : "=r"(a) : "l"(p));
    return a;
}
__device__ __forceinline__ void ldsm4(uint32_t addr, uint32_t* r) {
    asm volatile("ldmatrix.sync.aligned.m8n8.x4.shared.b16 {%0,%1,%2,%3}, [%4];"
        : "=r"(r[0]), "=r"(r[1]), "=r"(r[2]), "=r"(r[3]) : "r"(addr));
}
__device__ __forceinline__ void mma16816(float* c, const uint32_t* a, const uint32_t* b) {
    asm volatile(
        "mma.sync.aligned.m16n8k16.row.col.f32.f16.f16.f32 "
        "{%0,%1,%2,%3}, {%4,%5,%6,%7}, {%8,%9}, {%0,%1,%2,%3};"
        : "+f"(c[0]), "+f"(c[1]), "+f"(c[2]), "+f"(c[3])
        : "r"(a[0]), "r"(a[1]), "r"(a[2]), "r"(a[3]), "r"(b[0]), "r"(b[1]));
}
__device__ __forceinline__ uint32_t packh2(float v0, float v1) {
    __half2 h = __halves2half2(__float2half_rn(v0), __float2half_rn(v1));
    return *reinterpret_cast<uint32_t*>(&h);
}
__device__ __forceinline__ void cp16(uint32_t dst, const void* src) {
    asm volatile("cp.async.cg.shared.global [%0], [%1], 16;"
        :: "r"(dst), "l"(src) : "memory");
}
#define CP_COMMIT() asm volatile("cp.async.commit_group;" ::: "memory")
#define CP_WAIT0()  asm volatile("cp.async.wait_group 0;"  ::: "memory")

// ---------------------------------------------------------------------------
// fp16 GEMM via mma.sync:  C[M,N] = A[M,K] @ fp16(B)^T[N,K]  (+bias, relu)
//   A_F32 = true : A fp32; exact 2-pass split a = ah + al (both fp16)
//   A_F32 = false: A plain fp16 (lda elems), single pass (cp.async staged)
//   O_HALF: C written as fp16 (rounded), else fp32
//   CPX:    block.x==0 also copies its 128x64 fp32 A tile to xdst (ld 128)
//   BM=128, BK=32, 256 threads = 8 warps (4 M x 2 N).
//   Pipeline: double-buffered smem, ONE __syncthreads per chunk.
// ---------------------------------------------------------------------------
template<int BN, bool A_F32, bool O_HALF, bool RELU, bool BIAS, bool CPX>
__global__ void __launch_bounds__(256) mma_gemm(
    const void* __restrict__ Aptr, size_t lda,
    const __half* __restrict__ Bp,
    const float* __restrict__ bias,
    void* __restrict__ Cptr, size_t ldc,
    int K, float* __restrict__ xdst)
{
    constexpr int BM = 128, BK = 32;
    constexpr int APASS = A_F32 ? 2 : 1;
    constexpr int NG   = BN / 32;                 // B ldmatrix.x4 groups per k16
    constexpr int ABUF = BM * 40;                 // halves per A sub-buffer (80B rows)
    constexpr int BBUF = BN * 40;
    constexpr int STRIDE = APASS * ABUF + BBUF;   // halves per stage
    constexpr int NBV  = BN / 64;                 // 16B B copies per thread per chunk
    extern __shared__ __align__(16) __half smem[];

    const int tid = threadIdx.x, lane = tid & 31, wid = tid >> 5;
    const int wm = wid & 3, wn = wid >> 2;
    const size_t brow = (size_t)blockIdx.y * BM;
    const int bcol = blockIdx.x * BN;
    const int nc = K / BK;

    const float*  Af = (const float*)Aptr;
    const __half* Ab = (const __half*)Aptr;

    float4 afr[4];                                // A_F32 staging regs

    float acc[2][2 * NG][4];
    #pragma unroll
    for (int i = 0; i < 2; i++)
        #pragma unroll
        for (int j = 0; j < 2 * NG; j++)
            #pragma unroll
            for (int q = 0; q < 4; q++) acc[i][j][q] = 0.0f;

    const uint32_t sBase = smem_to_u32(smem);
    // lane-fixed ldmatrix byte offsets within a stage
    const uint32_t offA = (uint32_t)((wm * 32 + (lane & 15)) * 80 + (lane >> 4) * 16);
    const uint32_t rB   = (uint32_t)(wn * (BN / 2) + ((lane & 7) | (((lane >> 4) & 1) << 3)));
    const uint32_t offB = (uint32_t)(APASS * ABUF * 2) + rB * 80 + (((lane >> 3) & 1) * 16);

    // per-thread fixed smem copy slots
    const int rb4 = tid >> 2, cb4 = tid & 3;      // r = g>>2, c4 = g&3 (g = tid + i*256)

    // issue cp.async copies for chunk c into stage buf (B always; A if fp16)
    auto issue_cp = [&](int c, int buf) {
        const int k0 = c * BK;
        const uint32_t stage = sBase + (uint32_t)buf * (STRIDE * 2);
        if (!A_F32) {
            #pragma unroll
            for (int i = 0; i < 2; i++) {
                const int r = rb4 + i * 64;
                cp16(stage + (uint32_t)(r * 40 + cb4 * 8) * 2,
                     Ab + (brow + r) * lda + k0 + cb4 * 8);
            }
        }
        #pragma unroll
        for (int i = 0; i < NBV; i++) {
            const int r = rb4 + i * 64;
            cp16(stage + (uint32_t)(APASS * ABUF + r * 40 + cb4 * 8) * 2,
                 Bp + (size_t)(bcol + r) * K + k0 + cb4 * 8);
        }
        CP_COMMIT();
    };

    auto ldA_regs = [&](int c) {
        const int k0 = c * BK;
        #pragma unroll
        for (int i = 0; i < 4; i++) {
            const int g = tid + i * 256, r = g >> 3, c4 = g & 7;
            afr[i] = *reinterpret_cast<const float4*>(
                Af + (brow + r) * lda + k0 + c4 * 4);
        }
    };
    auto stA = [&](int buf) {
        __half* Ah = smem + buf * STRIDE;
        __half* Al = Ah + ABUF;
        #pragma unroll
        for (int i = 0; i < 4; i++) {
            const int g = tid + i * 256, r = g >> 3, c4 = g & 7;
            const float vv[4] = {afr[i].x, afr[i].y, afr[i].z, afr[i].w};
            float hf[4];
            #pragma unroll
            for (int j = 0; j < 4; j++)
                hf[j] = __half2float(__float2half_rn(vv[j]));
            const uint32_t H0 = packh2(vv[0], vv[1]);
            const uint32_t H1 = packh2(vv[2], vv[3]);
            const uint32_t L0 = packh2(vv[0] - hf[0], vv[1] - hf[1]);
            const uint32_t L1 = packh2(vv[2] - hf[2], vv[3] - hf[3]);
            *reinterpret_cast<uint2*>(Ah + r * 40 + c4 * 4) = make_uint2(H0, H1);
            *reinterpret_cast<uint2*>(Al + r * 40 + c4 * 4) = make_uint2(L0, L1);
        }
    };

    // prologue: stage 0
    if (A_F32) ldA_regs(0);
    issue_cp(0, 0);
    if (A_F32) stA(0);

    for (int c = 0; c < nc; c++) {
        const int buf = c & 1;
        CP_WAIT0();
        __syncthreads();                      // stage[buf] fully visible; buf^1 free
        if (c + 1 < nc) {
            if (A_F32) ldA_regs(c + 1);
            issue_cp(c + 1, buf ^ 1);
            if (A_F32) stA(buf ^ 1);          // writes buf^1, overlaps MMA on buf
        }
        const uint32_t stage = sBase + (uint32_t)buf * (STRIDE * 2);
        const uint32_t bAddr = stage + offB;
        #pragma unroll
        for (int kk = 0; kk < 2; kk++) {
            uint32_t b[NG][4];
            #pragma unroll
            for (int g = 0; g < NG; g++)
                ldsm4(bAddr + g * (16 * 80) + kk * 32, b[g]);
            #pragma unroll
            for (int p = 0; p < APASS; p++) {
                uint32_t a[2][4];
                const uint32_t aAddr = stage + (uint32_t)(p * ABUF * 2) + offA;
                #pragma unroll
                for (int mt = 0; mt < 2; mt++)
                    ldsm4(aAddr + mt * (16 * 80) + kk * 32, a[mt]);
                #pragma unroll
                for (int mt = 0; mt < 2; mt++)
                    #pragma unroll
                    for (int g = 0; g < NG; g++) {
                        mma16816(acc[mt][2 * g],     a[mt], &b[g][0]);
                        mma16816(acc[mt][2 * g + 1], a[mt], &b[g][2]);
                    }
            }
        }
    }

    // ---- optional x copy (GEMM1, block.x == 0): enc_gt[:, 0:64] = x ----
    if (CPX && blockIdx.x == 0) {
        #pragma unroll
        for (int i = 0; i < 8; i++) {
            const int g = tid + i * 256, r = g >> 4, cc = (g & 15) * 4;
            *reinterpret_cast<float4*>(xdst + (brow + r) * 128 + cc) =
                *reinterpret_cast<const float4*>(Af + (brow + r) * lda + cc);
        }
    }

    // ---- epilogue ----
    #pragma unroll
    for (int mt = 0; mt < 2; mt++) {
        #pragma unroll
        for (int nt = 0; nt < 2 * NG; nt++) {
            const size_t row = brow + wm * 32 + mt * 16 + (lane >> 2);
            const int    col = bcol + wn * (BN / 2) + nt * 8 + (lane & 3) * 2;
            float v0 = acc[mt][nt][0], v1 = acc[mt][nt][1];
            float v2 = acc[mt][nt][2], v3 = acc[mt][nt][3];
            if (BIAS) {
                const float bb0 = bias[col], bb1 = bias[col + 1];
                v0 += bb0; v1 += bb1; v2 += bb0; v3 += bb1;
            }
            if (RELU) {
                v0 = fmaxf(v0, 0.0f); v1 = fmaxf(v1, 0.0f);
                v2 = fmaxf(v2, 0.0f); v3 = fmaxf(v3, 0.0f);
            }
            if (O_HALF) {
                __half* Cb = (__half*)Cptr;
                *reinterpret_cast<uint32_t*>(Cb + row * ldc + col)       = packh2(v0, v1);
                *reinterpret_cast<uint32_t*>(Cb + (row + 8) * ldc + col) = packh2(v2, v3);
            } else {
                float* Cf = (float*)Cptr;
                *reinterpret_cast<float2*>(Cf + row * ldc + col)       = make_float2(v0, v1);
                *reinterpret_cast<float2*>(Cf + (row + 8) * ldc + col) = make_float2(v2, v3);
            }
        }
    }
}

// ---------------------------------------------------------------------------
// fp32 Koopman matrix powers (log-doubling) — exact
// ---------------------------------------------------------------------------
__global__ void init_powers(const float* __restrict__ ko)
{
    int i = blockIdx.x * blockDim.x + threadIdx.x;
    int r = i >> 7, c = i & 127;
    g_P[r * 8192 + c]       = (r == c) ? 1.0f : 0.0f;
    g_P[r * 8192 + 128 + c] = ko[i];
}

__global__ void __launch_bounds__(256) power_stage(int m)
{
    const int t = blockIdx.x + 1;
    if (m + t > 63) return;
    const float* Pt = g_P + t * 128;
    const float* Pm = g_P + m * 128;
    float*       Pd = g_P + (m + t) * 128;

    __shared__ float sPm [32][128];
    __shared__ float sPtT[32][128];

    const int tid   = threadIdx.x;
    const int r     = tid >> 1;
    const int cbase = (tid & 1) * 64;

    float acc[64];
    #pragma unroll
    for (int j = 0; j < 64; j++) acc[j] = 0.0f;

    for (int kk = 0; kk < 128; kk += 32) {
        #pragma unroll
        for (int i = tid; i < 32 * 128 / 4; i += 256) {
            int rr = i >> 5, cc = (i & 31) << 2;
            *reinterpret_cast<float4*>(&sPm[rr][cc]) =
                *reinterpret_cast<const float4*>(&Pm[(kk + rr) * 8192 + cc]);
        }
        #pragma unroll
        for (int i = tid; i < 128 * 32 / 4; i += 256) {
            int rr = i >> 3, cc = (i & 7) << 2;
            float4 v = *reinterpret_cast<const float4*>(&Pt[rr * 8192 + kk + cc]);
            sPtT[cc + 0][rr] = v.x; sPtT[cc + 1][rr] = v.y;
            sPtT[cc + 2][rr] = v.z; sPtT[cc + 3][rr] = v.w;
        }
        __syncthreads();
        #pragma unroll
        for (int k = 0; k < 32; k++) {
            const float a = sPtT[k][r];
            #pragma unroll
            for (int j = 0; j < 64; j += 4) {
                float4 bv = *reinterpret_cast<const float4*>(&sPm[k][cbase + j]);
                acc[j+0] = fmaf(a, bv.x, acc[j+0]);
                acc[j+1] = fmaf(a, bv.y, acc[j+1]);
                acc[j+2] = fmaf(a, bv.z, acc[j+2]);
                acc[j+3] = fmaf(a, bv.w, acc[j+3]);
            }
        }
        __syncthreads();
    }
    #pragma unroll
    for (int j = 0; j < 64; j += 4)
        *reinterpret_cast<float4*>(&Pd[r * 8192 + cbase + j]) =
            make_float4(acc[j], acc[j+1], acc[j+2], acc[j+3]);
}

// ---------------------------------------------------------------------------
// Prep: W[K][N] fp32 -> Bp[N][K] fp16 (transpose + round)
// ---------------------------------------------------------------------------
__global__ void prep_W(const float* __restrict__ W,
                       __half* __restrict__ Bp, int K, int N)
{
    int i = blockIdx.x * 256 + threadIdx.x;
    if (i >= N * K) return;
    int n = i / K, k = i - n * K;
    Bp[i] = __float2half_rn(W[(size_t)k * N + n]);
}

// Prep: g_P[k][n] (stride 8192) -> g_Pp[n][k] fp16
__global__ void prep_P()
{
    int i = blockIdx.x * 256 + threadIdx.x;   // 8192*128
    int n = i >> 7, k = i & 127;
    g_Pp[i] = __float2half_rn(g_P[k * 8192 + n]);
}

// ---------------------------------------------------------------------------
// kernel_launch — graph-capturable (kernel launches only)
// Input order: x, W0, b0, W1, b1, W2, ko_W, n_shifts
// ---------------------------------------------------------------------------
extern "C" void kernel_launch(void* const* d_in, const int* in_sizes, int n_in,
                              void* d_out, int out_size)
{
    const float* x   = (const float*)d_in[0];
    const float* W0  = (const float*)d_in[1];
    const float* b0  = (const float*)d_in[2];
    const float* W1  = (const float*)d_in[3];
    const float* b1  = (const float*)d_in[4];
    const float* W2  = (const float*)d_in[5];
    const float* koW = (const float*)d_in[6];
    (void)in_sizes; (void)n_in; (void)out_size;

    float* out      = (float*)d_out;
    float* enc_gt   = out;
    float* enc_traj = out + ENC_GT_ELEMS;

    __half *h1, *h2, *Bp0, *Bp1, *Bp2, *Pp;
    cudaGetSymbolAddress((void**)&h1,  g_h1);
    cudaGetSymbolAddress((void**)&h2,  g_h2);
    cudaGetSymbolAddress((void**)&Bp0, g_Bp0);
    cudaGetSymbolAddress((void**)&Bp1, g_Bp1);
    cudaGetSymbolAddress((void**)&Bp2, g_Bp2);
    cudaGetSymbolAddress((void**)&Pp,  g_Pp);

    // dynamic smem per variant: STRIDE halves * 2 stages * 2 bytes
    const int SM_SPLIT128 = (2 * 128 + 128) * 40 * 2 * 2;  // 61440 (A_F32, BN=128)
    const int SM_H128     = (128 + 128) * 40 * 2 * 2;      // 40960 (fp16 A, BN=128)
    const int SM_H64      = (128 + 64)  * 40 * 2 * 2;      // 30720 (fp16 A, BN=64)
    cudaFuncSetAttribute(mma_gemm<128, true,  true,  true,  true,  true >, cudaFuncAttributeMaxDynamicSharedMemorySize, SM_SPLIT128);
    cudaFuncSetAttribute(mma_gemm<128, false, true,  true,  true,  false>, cudaFuncAttributeMaxDynamicSharedMemorySize, SM_H128);
    cudaFuncSetAttribute(mma_gemm<64,  false, false, false, false, false>, cudaFuncAttributeMaxDynamicSharedMemorySize, SM_H64);
    cudaFuncSetAttribute(mma_gemm<128, true,  false, false, false, false>, cudaFuncAttributeMaxDynamicSharedMemorySize, SM_SPLIT128);

    // weight prep (round + transpose to [N][K] fp16)
    prep_W<<<64,  256>>>(W0, Bp0, 64, 256);
    prep_W<<<256, 256>>>(W1, Bp1, 256, 256);
    prep_W<<<64,  256>>>(W2, Bp2, 256, 64);

    // h1 = relu(x @ W0 + b0)           M=524288 K=64  N=256  (+ x copy to enc_gt)
    mma_gemm<128, true, true, true, true, true><<<dim3(2, MROWS / 128), 256, SM_SPLIT128>>>(
        x, 64, Bp0, b0, h1, 256, 64, enc_gt);

    // h2 = relu(h1 @ W1 + b1)          M=524288 K=256 N=256  (fp16 in/out, 1-pass)
    mma_gemm<128, false, true, true, true, false><<<dim3(2, MROWS / 128), 256, SM_H128>>>(
        h1, 256, Bp1, b1, h2, 256, 256, nullptr);

    // enc_gt cols [64,128) = h2 @ W2   M=524288 K=256 N=64   (fp16 in, fp32 out, 1-pass)
    mma_gemm<64, false, false, false, false, false><<<dim3(1, MROWS / 128), 256, SM_H64>>>(
        h2, 256, Bp2, nullptr, enc_gt + 64, 128, 256, nullptr);

    // fp32 Koopman powers, then round for the trajectory GEMM
    init_powers<<<64, 256>>>(koW);
    for (int m = 1; m <= 32; m <<= 1)
        power_stage<<<m, 256>>>(m);
    prep_P<<<4096, 256>>>();

    // enc_traj = z0 @ [P_0 | ... | P_63]   M=8192 K=128 N=8192 (2-pass exact A)
    mma_gemm<128, true, false, false, false, false><<<dim3(64, 64), 256, SM_SPLIT128>>>(
        enc_gt, 8192, Pp, nullptr, enc_traj, 8192, 128, nullptr);
}